// round 12
// baseline (speedup 1.0000x reference)
#include <cuda_runtime.h>
#include <cuda_bf16.h>
#include <cstdint>

#define M_TOT   8192
#define K_IN    4096
#define RANK    256
#define N_OUT   4096
#define VERA_SCALE (32.0f / 256.0f)

// pre-split bf16 hi/lo planes (packed 2 elems per uint32, row-major)
__device__ uint32_t g_Ahi[(size_t)RANK * K_IN / 2];
__device__ uint32_t g_Alo[(size_t)RANK * K_IN / 2];
__device__ uint32_t g_Bhi[(size_t)N_OUT * RANK / 2];
__device__ uint32_t g_Blo[(size_t)N_OUT * RANK / 2];
__device__ uint32_t g_Xhi[(size_t)M_TOT * K_IN / 2];
__device__ uint32_t g_Xlo[(size_t)M_TOT * K_IN / 2];
// split-K partials for GEMM1 and the split intermediate t
__device__ float    g_p[2][(size_t)M_TOT * RANK];
__device__ uint32_t g_thi[(size_t)M_TOT * RANK / 2];
__device__ uint32_t g_tlo[(size_t)M_TOT * RANK / 2];

// ------------- helpers -------------
__device__ __forceinline__ uint32_t smem_u32(const void* p) {
    uint32_t a;
    asm("{ .reg .u64 t; cvta.to.shared.u64 t, %1; cvt.u32.u64 %0, t; }" : "=r"(a) : "l"(p));
    return a;
}
__device__ __forceinline__ void ldsm4(uint32_t r[4], uint32_t addr) {
    asm volatile("ldmatrix.sync.aligned.m8n8.x4.shared.b16 {%0,%1,%2,%3}, [%4];"
                 : "=r"(r[0]), "=r"(r[1]), "=r"(r[2]), "=r"(r[3]) : "r"(addr));
}
__device__ __forceinline__ void mma_bf16(float c[4], const uint32_t a[4],
                                         uint32_t b0, uint32_t b1) {
    asm volatile(
        "mma.sync.aligned.m16n8k16.row.col.f32.bf16.bf16.f32 "
        "{%0,%1,%2,%3}, {%4,%5,%6,%7}, {%8,%9}, {%0,%1,%2,%3};"
        : "+f"(c[0]), "+f"(c[1]), "+f"(c[2]), "+f"(c[3])
        : "r"(a[0]), "r"(a[1]), "r"(a[2]), "r"(a[3]), "r"(b0), "r"(b1));
}
// SW64 swizzle: XOR byte-offset bits [5:4] with bits [8:7] (64B rows)
__device__ __forceinline__ uint32_t sw64(uint32_t b) {
    return b ^ ((b >> 3) & 0x30);
}
__device__ __forceinline__ void split2(float a, float b, uint32_t& hi, uint32_t& lo) {
    uint32_t ua = __float_as_uint(a), ub = __float_as_uint(b);
    hi = __byte_perm(ua, ub, 0x7632);
    float fa = __uint_as_float(ua & 0xFFFF0000u);
    float fb = __uint_as_float(ub & 0xFFFF0000u);
    float la = a - fa, lb = b - fb;
    asm("cvt.rn.bf16x2.f32 %0, %1, %2;" : "=r"(lo) : "f"(lb), "f"(la));
}
__device__ __forceinline__ void cpa16(uint32_t dst, const void* src) {
    asm volatile("cp.async.cg.shared.global [%0], [%1], 16;" :: "r"(dst), "l"(src));
}
#define CP_COMMIT() asm volatile("cp.async.commit_group;" ::: "memory")
#define CP_WAIT2()  asm volatile("cp.async.wait_group 2;" ::: "memory")

// one-shot pre-split: fp32 matrix -> planar packed-bf16 hi/lo
__global__ void split_kernel(const float4* __restrict__ in, uint32_t* __restrict__ hi,
                             uint32_t* __restrict__ lo, int n4) {
    int i = blockIdx.x * blockDim.x + threadIdx.x;
    if (i < n4) {
        float4 v = in[i];
        uint32_t h0, l0, h1, l1;
        split2(v.x, v.y, h0, l0);
        split2(v.z, v.w, h1, l1);
        hi[2 * i] = h0; hi[2 * i + 1] = h1;
        lo[2 * i] = l0; lo[2 * i + 1] = l1;
    }
}

// combine split-K partials, scale by d_A, emit split hi/lo t
__global__ void combine_kernel(const float* __restrict__ p0, const float* __restrict__ p1,
                               const float* __restrict__ dA,
                               uint32_t* __restrict__ thi, uint32_t* __restrict__ tlo,
                               int n4) {
    int i = blockIdx.x * blockDim.x + threadIdx.x;
    if (i < n4) {
        float4 a = reinterpret_cast<const float4*>(p0)[i];
        float4 b = reinterpret_cast<const float4*>(p1)[i];
        int col = (i * 4) & (RANK - 1);
        float4 s = *reinterpret_cast<const float4*>(dA + col);
        uint32_t h, l;
        split2((a.x + b.x) * s.x, (a.y + b.y) * s.y, h, l);
        thi[2 * i] = h; tlo[2 * i] = l;
        split2((a.z + b.z) * s.z, (a.w + b.w) * s.w, h, l);
        thi[2 * i + 1] = h; tlo[2 * i + 1] = l;
    }
}

// ============ shared GEMM core ============
// GEMM-NT on pre-split operands. CTA 128x256, K-chunk 32 (64B SMEM rows, SW64),
// 4-stage cp.async pipeline. 512 threads = 16 warps (4m x 4n), warp tile 32x64.
template <int NCHUNKS, int A_STRIDE_U32, int B_STRIDE_U32>
__device__ __forceinline__ void gemm_core(
    const uint32_t* __restrict__ Ahi_, const uint32_t* __restrict__ Alo_,
    const uint32_t* __restrict__ Bhi_, const uint32_t* __restrict__ Blo_,
    int bm, int bn, int koff_u32, char* smem, float acc[2][8][4])
{
    constexpr int AP = 8192, BP = 16384;
    constexpr int STAGE = 2 * AP + 2 * BP;   // 48KB
    const uint32_t sb = smem_u32(smem);

    const int tid = threadIdx.x, wid = tid >> 5, lid = tid & 31;
    const int warp_m = wid & 3, warp_n = wid >> 2;

    const int rowA = warp_m * 32 + (lid & 15);
    const uint32_t pA0 = (uint32_t)(rowA * 64), pA1 = pA0 + 1024;
    const uint32_t kbA = (uint32_t)((lid >> 4) * 16);
    const uint32_t xA  = (uint32_t)(((rowA >> 1) & 3) << 4);
    const int rowB = warp_n * 64 + ((lid >> 4) * 8 + (lid & 7));
    const uint32_t pB0 = (uint32_t)(rowB * 64);
    const uint32_t kbB = (uint32_t)(((lid >> 3) & 1) * 16);
    const uint32_t xB  = (uint32_t)(((rowB >> 1) & 3) << 4);

    const int frow = tid >> 2, fc16 = tid & 3;   // fill mapping: 128 rows x 4 c16

    auto fill = [&](uint32_t dstb, int c) {
        const int col = koff_u32 + c * 16 + fc16 * 4;
        {
            uint32_t off = sw64((uint32_t)(frow * 64 + fc16 * 16));
            cpa16(dstb + off,      Ahi_ + (size_t)(bm + frow) * A_STRIDE_U32 + col);
            cpa16(dstb + AP + off, Alo_ + (size_t)(bm + frow) * A_STRIDE_U32 + col);
        }
        #pragma unroll
        for (int j = 0; j < 2; ++j) {
            int row = frow + j * 128;
            uint32_t off = sw64((uint32_t)(row * 64 + fc16 * 16));
            cpa16(dstb + 2 * AP + off,      Bhi_ + (size_t)(bn + row) * B_STRIDE_U32 + col);
            cpa16(dstb + 2 * AP + BP + off, Blo_ + (size_t)(bn + row) * B_STRIDE_U32 + col);
        }
    };

    // prologue: fill stages 0..2 (one commit group each)
    #pragma unroll
    for (int p = 0; p < 3; ++p) {
        if (p < NCHUNKS) fill(sb + (uint32_t)(p * STAGE), p);
        CP_COMMIT();
    }

    for (int ch = 0; ch < NCHUNKS; ++ch) {
        CP_WAIT2();            // chunk ch's fill complete (<=2 newer groups pending)
        __syncthreads();       // visibility + stage-reuse safety
        const uint32_t base = sb + (uint32_t)((ch & 3) * STAGE);
        if (ch + 3 < NCHUNKS) fill(sb + (uint32_t)(((ch + 3) & 3) * STAGE), ch + 3);
        CP_COMMIT();           // always commit (empty group at tail keeps count exact)

        #pragma unroll
        for (int s = 0; s < 2; ++s) {
            const uint32_t aoff = ((uint32_t)(s * 32) + kbA) ^ xA;
            const uint32_t boff = ((uint32_t)(s * 32) + kbB) ^ xB;
            uint32_t ah[2][4], al[2][4];
            ldsm4(ah[0], base + pA0 + aoff);
            ldsm4(ah[1], base + pA1 + aoff);
            ldsm4(al[0], base + AP + pA0 + aoff);
            ldsm4(al[1], base + AP + pA1 + aoff);

            #pragma unroll
            for (int g = 0; g < 2; ++g) {
                uint32_t bh[2][4], bl[2][4];
                const uint32_t nb = base + 2 * AP + pB0 + boff + (uint32_t)(g * 2048);
                ldsm4(bh[0], nb);
                ldsm4(bh[1], nb + 1024);
                ldsm4(bl[0], nb + BP);
                ldsm4(bl[1], nb + BP + 1024);
                #pragma unroll
                for (int np = 0; np < 2; ++np)
                    #pragma unroll
                    for (int mi = 0; mi < 2; ++mi) {
                        const int j = (g * 2 + np) * 2;
                        mma_bf16(acc[mi][j],     ah[mi], bh[np][0], bh[np][1]);
                        mma_bf16(acc[mi][j + 1], ah[mi], bh[np][2], bh[np][3]);
                    }
                #pragma unroll
                for (int np = 0; np < 2; ++np)
                    #pragma unroll
                    for (int mi = 0; mi < 2; ++mi) {
                        const int j = (g * 2 + np) * 2;
                        mma_bf16(acc[mi][j],     ah[mi], bl[np][0], bl[np][1]);
                        mma_bf16(acc[mi][j + 1], ah[mi], bl[np][2], bl[np][3]);
                    }
                #pragma unroll
                for (int np = 0; np < 2; ++np)
                    #pragma unroll
                    for (int mi = 0; mi < 2; ++mi) {
                        const int j = (g * 2 + np) * 2;
                        mma_bf16(acc[mi][j],     al[mi], bh[np][0], bh[np][1]);
                        mma_bf16(acc[mi][j + 1], al[mi], bh[np][2], bh[np][3]);
                    }
            }
        }
    }
    __syncthreads();
}

// GEMM1: partial[m][r] = sum_{k in split} X[m][k]*A[r][k]
__global__ __launch_bounds__(512, 1)
void vera_g1(const uint32_t* __restrict__ Xhi_, const uint32_t* __restrict__ Xlo_,
             const uint32_t* __restrict__ Ahi_, const uint32_t* __restrict__ Alo_,
             float* __restrict__ Part)
{
    extern __shared__ char smem[];
    const int bm = blockIdx.x * 128;
    const int split = blockIdx.y;
    float* Out = Part + (size_t)split * M_TOT * RANK;

    float acc[2][8][4];
    #pragma unroll
    for (int i = 0; i < 2; ++i)
        #pragma unroll
        for (int j = 0; j < 8; ++j)
            #pragma unroll
            for (int q = 0; q < 4; ++q) acc[i][j][q] = 0.0f;

    // split k: 64 chunks of 32 starting at u32 col split*1024
    gemm_core<64, K_IN / 2, K_IN / 2>(Xhi_, Xlo_, Ahi_, Alo_, bm, 0,
                                      split * 1024, smem, acc);

    const int tid = threadIdx.x, wid = tid >> 5, lid = tid & 31;
    const int warp_m = wid & 3, warp_n = wid >> 2;
    const int mrow0 = bm + warp_m * 32 + (lid >> 2);
    const int nc0   = warp_n * 64 + (lid & 3) * 2;
    #pragma unroll
    for (int mi = 0; mi < 2; ++mi) {
        #pragma unroll
        for (int nj = 0; nj < 8; ++nj) {
            const int n = nc0 + nj * 8;
            const int m0 = mrow0 + mi * 16;
            *reinterpret_cast<float2*>(Out + (size_t)m0 * RANK + n) =
                make_float2(acc[mi][nj][0], acc[mi][nj][1]);
            *reinterpret_cast<float2*>(Out + (size_t)(m0 + 8) * RANK + n) =
                make_float2(acc[mi][nj][2], acc[mi][nj][3]);
        }
    }
}

// GEMM2: out[m][o] = (sum_r t[m][r]*B[o][r]) * d_B[o] * SCALE
__global__ __launch_bounds__(512, 1)
void vera_g2(const uint32_t* __restrict__ Thi_, const uint32_t* __restrict__ Tlo_,
             const uint32_t* __restrict__ Bhi_, const uint32_t* __restrict__ Blo_,
             const float* __restrict__ dB, float* __restrict__ Out)
{
    extern __shared__ char smem[];
    constexpr int STAGE = 2 * 8192 + 2 * 16384;
    float* cs = reinterpret_cast<float*>(smem + 4 * STAGE);
    const int bm = blockIdx.x * 128;
    const int bn = blockIdx.y * 256;
    const int tid = threadIdx.x;

    if (tid < 256) cs[tid] = dB[bn + tid] * VERA_SCALE;

    float acc[2][8][4];
    #pragma unroll
    for (int i = 0; i < 2; ++i)
        #pragma unroll
        for (int j = 0; j < 8; ++j)
            #pragma unroll
            for (int q = 0; q < 4; ++q) acc[i][j][q] = 0.0f;

    gemm_core<8, RANK / 2, RANK / 2>(Thi_, Tlo_, Bhi_, Blo_, bm, bn, 0, smem, acc);

    const int wid = tid >> 5, lid = tid & 31;
    const int warp_m = wid & 3, warp_n = wid >> 2;
    const int mrow0 = bm + warp_m * 32 + (lid >> 2);
    const int nc0   = warp_n * 64 + (lid & 3) * 2;
    #pragma unroll
    for (int mi = 0; mi < 2; ++mi) {
        #pragma unroll
        for (int nj = 0; nj < 8; ++nj) {
            const int n = nc0 + nj * 8;
            const float s0 = cs[n], s1 = cs[n + 1];
            float2 v0, v1;
            v0.x = acc[mi][nj][0] * s0; v0.y = acc[mi][nj][1] * s1;
            v1.x = acc[mi][nj][2] * s0; v1.y = acc[mi][nj][3] * s1;
            const int m0 = mrow0 + mi * 16;
            *reinterpret_cast<float2*>(Out + (size_t)m0 * N_OUT + bn + n) = v0;
            *reinterpret_cast<float2*>(Out + (size_t)(m0 + 8) * N_OUT + bn + n) = v1;
        }
    }
}

extern "C" void kernel_launch(void* const* d_in, const int* in_sizes, int n_in,
                              void* d_out, int out_size)
{
    const float* x   = (const float*)d_in[0];  // [8192][4096]
    const float* A   = (const float*)d_in[1];  // [256][4096]
    const float* B   = (const float*)d_in[2];  // [4096][256]
    const float* d_A = (const float*)d_in[3];  // [256]
    const float* d_B = (const float*)d_in[4];  // [4096]
    float* out = (float*)d_out;                // [8192][4096]

    uint32_t *Ahi, *Alo, *Bhi, *Blo, *Xhi, *Xlo, *thi, *tlo;
    float* part;
    cudaGetSymbolAddress((void**)&Ahi, g_Ahi);
    cudaGetSymbolAddress((void**)&Alo, g_Alo);
    cudaGetSymbolAddress((void**)&Bhi, g_Bhi);
    cudaGetSymbolAddress((void**)&Blo, g_Blo);
    cudaGetSymbolAddress((void**)&Xhi, g_Xhi);
    cudaGetSymbolAddress((void**)&Xlo, g_Xlo);
    cudaGetSymbolAddress((void**)&thi, g_thi);
    cudaGetSymbolAddress((void**)&tlo, g_tlo);
    cudaGetSymbolAddress((void**)&part, g_p);

    constexpr int SMEM = 4 * (2 * 8192 + 2 * 16384) + 1024;   // 197632
    cudaFuncSetAttribute(vera_g1, cudaFuncAttributeMaxDynamicSharedMemorySize, SMEM);
    cudaFuncSetAttribute(vera_g2, cudaFuncAttributeMaxDynamicSharedMemorySize, SMEM);

    // pre-split A, B, X
    {
        int n4 = RANK * K_IN / 4;
        split_kernel<<<n4 / 256, 256>>>((const float4*)A, Ahi, Alo, n4);
        int n4b = N_OUT * RANK / 4;
        split_kernel<<<n4b / 256, 256>>>((const float4*)B, Bhi, Blo, n4b);
        int n4x = M_TOT * K_IN / 4;
        split_kernel<<<n4x / 256, 256>>>((const float4*)x, Xhi, Xlo, n4x);
    }
    // GEMM1 split-K=2: partials
    {
        dim3 grid(M_TOT / 128, 2);      // 128 CTAs
        vera_g1<<<grid, 512, SMEM>>>(Xhi, Xlo, Ahi, Alo, part);
    }
    // combine + d_A scale + split t
    {
        int n4 = M_TOT * RANK / 4;
        combine_kernel<<<n4 / 256, 256>>>(part, part + (size_t)M_TOT * RANK,
                                          d_A, thi, tlo, n4);
    }
    // GEMM2
    {
        dim3 grid(M_TOT / 128, N_OUT / 256);  // 64 x 16
        vera_g2<<<grid, 512, SMEM>>>(thi, tlo, Bhi, Blo, d_B, out);
    }
}